// round 9
// baseline (speedup 1.0000x reference)
#include <cuda_runtime.h>

#define NWIRES 11
#define NLAY   4
#define NGATES 88
#define PIX    1024
#define NB     1024

typedef unsigned long long ull;

// Per gate: (c1,d1,c2,d2) = (u00.re, u00.im, u01.re, u01.im); SU(2): u10=(-c2,d2), u11=(c1,-d1)
__device__ float4 g_G[NGATES];

__global__ void precompute_gates(const float* __restrict__ w0,
                                 const float* __restrict__ w1) {
    int idx = blockIdx.x * blockDim.x + threadIdx.x;
    if (idx >= NGATES) return;
    const float PI_F = 3.14159265358979323846f;
    int k = idx / 44, rem = idx % 44;
    const float* w = (k == 0) ? w0 : w1;
    float phi   = PI_F * tanhf(w[rem * 3 + 0]);
    float theta = PI_F * tanhf(w[rem * 3 + 1]);
    float omega = PI_F * tanhf(w[rem * 3 + 2]);
    float c = cosf(0.5f * theta), s = sinf(0.5f * theta);
    float apo = 0.5f * (phi + omega), bpo = 0.5f * (phi - omega);
    float are = cosf(apo), aim = -sinf(apo);   // a = exp(-i*apo)
    float bre = cosf(bpo), bim = sinf(bpo);    // b = exp(+i*bpo)
    g_G[idx] = make_float4(are * c, aim * c, -bre * s, -bim * s);
}

// inverse CNOT-chain permutation (gather form); GF(2)-linear in dst.
__device__ __forceinline__ int cinv_idx(int dst, int r) {
    int src = dst;
    for (int q = NWIRES - 1; q >= 0; q--) {
        int cb = NWIRES - 1 - q;
        int tq = q + r; if (tq >= NWIRES) tq -= NWIRES;
        int tbit = NWIRES - 1 - tq;
        src ^= ((src >> cb) & 1) << tbit;
    }
    return src;
}
// amp index s -> float offset of its re part in the pair smem layout
__device__ __forceinline__ int fmap(int s) { return ((s >> 1) << 2) | (s & 1); }

// ---- packed f32x2 helpers ----
__device__ __forceinline__ ull pk(float lo, float hi) {
    ull r; asm("mov.b64 %0,{%1,%2};" : "=l"(r) : "f"(lo), "f"(hi)); return r;
}
__device__ __forceinline__ void upk(ull v, float& lo, float& hi) {
    asm("mov.b64 {%0,%1},%2;" : "=f"(lo), "=f"(hi) : "l"(v));
}
__device__ __forceinline__ ull dup2(float v) { return pk(v, v); }
__device__ __forceinline__ ull m2(ull a, ull b) {
    ull d; asm("mul.rn.f32x2 %0,%1,%2;" : "=l"(d) : "l"(a), "l"(b)); return d;
}
__device__ __forceinline__ ull f2(ull a, ull b, ull c) {
    ull d; asm("fma.rn.f32x2 %0,%1,%2,%3;" : "=l"(d) : "l"(a), "l"(b), "l"(c)); return d;
}

// SU(2) gate on an inter-register bit (broadcast packed form). flip swaps 0/1 roles.
__device__ __forceinline__ void gate_reg(ull aRe[8], ull aIm[8], float4 g,
                                         int stride, bool flip) {
    float c1 = g.x, d1 = flip ? -g.y : g.y, c2 = flip ? -g.z : g.z, d2 = g.w;
    ull C1 = dup2(c1), D1 = dup2(d1), ND1 = dup2(-d1);
    ull C2 = dup2(c2), NC2 = dup2(-c2), D2 = dup2(d2), ND2 = dup2(-d2);
    #pragma unroll
    for (int j0 = 0; j0 < 8; j0++) {
        if (j0 & stride) continue;
        int j1 = j0 | stride;
        ull A0r = aRe[j0], A0i = aIm[j0], A1r = aRe[j1], A1i = aIm[j1];
        ull o0r = f2(ND2, A1i, f2(C2, A1r, f2(ND1, A0i, m2(C1, A0r))));
        ull o0i = f2(C2,  A1i, f2(D2, A1r, f2(C1,  A0i, m2(D1, A0r))));
        ull o1r = f2(D1,  A1i, f2(C1, A1r, f2(ND2, A0i, m2(NC2, A0r))));
        ull o1i = f2(C1,  A1i, f2(ND1,A1r, f2(NC2, A0i, m2(D2,  A0r))));
        aRe[j0] = o0r; aIm[j0] = o0i; aRe[j1] = o1r; aIm[j1] = o1i;
    }
}

// SU(2) gate on lane bit 0 (partner via shfl)
__device__ __forceinline__ void gate_shfl(ull aRe[8], ull aIm[8], float4 g, int hi) {
    float sd1 = hi ? -g.y : g.y;     // csy
    float sc2 = hi ? -g.z : g.z;     // cox
    ull CSX = dup2(g.x), CSY = dup2(sd1), NCSY = dup2(-sd1);
    ull COX = dup2(sc2), COY = dup2(g.w), NCOY = dup2(-g.w);
    #pragma unroll
    for (int j = 0; j < 8; j++) {
        ull Pr = __shfl_xor_sync(0xffffffffu, aRe[j], 1);
        ull Pi = __shfl_xor_sync(0xffffffffu, aIm[j], 1);
        ull Or = f2(NCOY, Pi, f2(COX, Pr, f2(NCSY, aIm[j], m2(CSX, aRe[j]))));
        ull Oi = f2(COX,  Pi, f2(COY, Pr, f2(CSX,  aIm[j], m2(CSY, aRe[j]))));
        aRe[j] = Or; aIm[j] = Oi;
    }
}

// SU(2) gate on the packing bit (intra-register butterfly via swapped halves)
__device__ __forceinline__ void gate_intra(ull aRe[8], ull aIm[8], float4 g) {
    float c1 = g.x, d1 = g.y, c2 = g.z, d2 = g.w;
    ull K1 = dup2(c1), K2 = pk(c2, -c2), K3 = pk(-d1, d1), K4 = dup2(-d2);
    ull K5 = pk(d1, -d1), K6 = dup2(d2);
    #pragma unroll
    for (int j = 0; j < 8; j++) {
        float rl, rh, il, ih;
        upk(aRe[j], rl, rh); upk(aIm[j], il, ih);
        ull Sr = pk(rh, rl), Si = pk(ih, il);
        ull Or = f2(K4, Si, f2(K3, aIm[j], f2(K2, Sr, m2(K1, aRe[j]))));
        ull Oi = f2(K2, Si, f2(K1, aIm[j], f2(K6, Sr, m2(K5, aRe[j]))));
        aRe[j] = Or; aIm[j] = Oi;
    }
}

__global__ __launch_bounds__(128, 8)
void qsim_kernel(const float* __restrict__ x,
                 const float* __restrict__ y,
                 float* __restrict__ out) {
    // pair P: 16 bytes = (re0,re1,im0,im1) == (ull rePair, ull imPair)
    __shared__ ulonglong2 sm2[1024];   // 16 KB single buffer
    __shared__ int fR[4][8];           // fmap(Cinv(j<<8, r))
    __shared__ int fW[4];              // fmap(Cinv(1, r))
    __shared__ float red[4];
    float* smf = (float*)sm2;

    const int b = blockIdx.x, t = threadIdx.x;
    const float* xb = x + (size_t)b * PIX;

    // ---- tiny perm tables + per-thread bases (GF(2)-linear decomposition) ----
    if (t < 32) fR[t >> 3][t & 7] = fmap(cinv_idx((t & 7) << 8, (t >> 3) + 1));
    if (t < 4)  fW[t] = fmap(cinv_idx(1, t + 1));
    int baseR[4];
    #pragma unroll
    for (int r = 0; r < 4; r++) baseR[r] = fmap(cinv_idx(t << 1, r + 1));

    // ---- norm ----
    float ss = 0.0f;
    #pragma unroll
    for (int i = t; i < PIX; i += 128) { float v = xb[i]; ss += v * v; }
    #pragma unroll
    for (int o = 16; o > 0; o >>= 1) ss += __shfl_xor_sync(0xffffffffu, ss, o);
    if ((t & 31) == 0) red[t >> 5] = ss;
    __syncthreads();
    float inv = 1.0f / sqrtf(red[0] + red[1] + red[2] + red[3]);

    // ---- embedding: pair P = (emb[P], 0 | 0, 0) ----
    #pragma unroll
    for (int s8 = 0; s8 < 8; s8++) {
        int P = t + (s8 << 7);
        sm2[P] = make_ulonglong2(pk(xb[P] * inv, 0.0f), 0ull);
    }
    const float yhalf = 0.5f * y[b];
    const float yc = cosf(yhalf), ys = sinf(yhalf);
    __syncthreads();

    ull aRe[8], aIm[8];
    const int t31 = (t >> 1) & 7;
    const int B3x = ((t >> 1) << 4) | (t31 << 1) | (t & 1);
    const int b2  = ((t >> 4) << 7) | (t & 15);

    #pragma unroll 1
    for (int k = 0; k < 2; k++) {
        #pragma unroll 1
        for (int l = 0; l < NLAY; l++) {
            const int gbase = k * 44 + l * 11;
            const int pend = (k == 0 && l == 0) ? 0 : ((l == 0) ? 4 : l);

            // ===== pass 1: reg bits = i[10:8] (wires 0,1,2); perm folded into gather.
            //       Single buffer: ALL scattered reads complete (barrier after the
            //       register-only gates) before ANY linear write. =====
            if (pend == 0) {
                #pragma unroll
                for (int r = 0; r < 8; r++) {
                    ulonglong2 v = sm2[(r << 7) | t];
                    aRe[r] = v.x; aIm[r] = v.y;
                }
            } else {
                const int base = baseR[pend - 1], wv = fW[pend - 1];
                #pragma unroll
                for (int r = 0; r < 8; r++) {
                    int A0 = base ^ fR[pend - 1][r];
                    int A1 = A0 ^ wv;
                    aRe[r] = pk(smf[A0], smf[A1]);
                    aIm[r] = pk(smf[A0 + 2], smf[A1 + 2]);
                }
            }
            gate_reg(aRe, aIm, g_G[gbase + 0], 4, false);
            gate_reg(aRe, aIm, g_G[gbase + 1], 2, false);
            gate_reg(aRe, aIm, g_G[gbase + 2], 1, false);
            __syncthreads();   // reads-before-writes fence (race fix)
            #pragma unroll
            for (int r = 0; r < 8; r++)
                sm2[(r << 7) | t] = make_ulonglong2(aRe[r], aIm[r]);
            __syncthreads();

            // ===== pass 2: reg bits = i[7:5] (wires 3,4,5); per-thread in-place safe =====
            #pragma unroll
            for (int r = 0; r < 8; r++) {
                ulonglong2 v = sm2[b2 | (r << 4)];
                aRe[r] = v.x; aIm[r] = v.y;
            }
            gate_reg(aRe, aIm, g_G[gbase + 3], 4, false);
            gate_reg(aRe, aIm, g_G[gbase + 4], 2, false);
            gate_reg(aRe, aIm, g_G[gbase + 5], 1, false);
            #pragma unroll
            for (int r = 0; r < 8; r++)
                sm2[b2 | (r << 4)] = make_ulonglong2(aRe[r], aIm[r]);
            __syncthreads();

            // ===== pass 3: reg bits = i[4:2] (wires 6,7,8) XOR-relabeled (flip trick);
            //       wire 9 shfl on lane bit 0; wire 10 intra; per-thread in-place safe =====
            #pragma unroll
            for (int u = 0; u < 8; u++) {
                ulonglong2 v = sm2[B3x ^ (u << 1)];
                aRe[u] = v.x; aIm[u] = v.y;
            }
            gate_reg(aRe, aIm, g_G[gbase + 6], 4, (t31 >> 2) & 1);
            gate_reg(aRe, aIm, g_G[gbase + 7], 2, (t31 >> 1) & 1);
            gate_reg(aRe, aIm, g_G[gbase + 8], 1, t31 & 1);
            gate_shfl(aRe, aIm, g_G[gbase + 9], t & 1);
            {
                float4 G = g_G[gbase + 10];
                if (l == 0) {   // fuse RX(y): F = Rot * RX
                    float c1 = G.x, d1 = G.y, c2 = G.z, d2 = G.w;
                    G = make_float4(c1 * yc + d2 * ys, d1 * yc - c2 * ys,
                                    d1 * ys + c2 * yc, -c1 * ys + d2 * yc);
                }
                gate_intra(aRe, aIm, G);
            }
            #pragma unroll
            for (int u = 0; u < 8; u++)
                sm2[B3x ^ (u << 1)] = make_ulonglong2(aRe[u], aIm[u]);
            __syncthreads();
        }
    }

    // ---- epilogue: final perm (r=4) folded; probs of even basis states ----
    float* ob = out + (size_t)b * PIX;
    const int baseo = baseR[3];
    #pragma unroll
    for (int s8 = 0; s8 < 8; s8++) {
        int addr = baseo ^ fR[3][s8];
        float re = smf[addr], im = smf[addr + 2];
        float pr = (re * re + im * im) * 1024.0f;
        ob[(s8 << 7) + t] = fminf(pr, 1.0f);
    }
}

extern "C" void kernel_launch(void* const* d_in, const int* in_sizes, int n_in,
                              void* d_out, int out_size) {
    const float* x  = (const float*)d_in[0];
    const float* y  = (const float*)d_in[1];
    const float* w0 = (const float*)d_in[2];
    const float* w1 = (const float*)d_in[3];
    float* out = (float*)d_out;

    precompute_gates<<<1, 128>>>(w0, w1);
    qsim_kernel<<<NB, 128>>>(x, y, out);
}

// round 10
// speedup vs baseline: 1.0043x; 1.0043x over previous
#include <cuda_runtime.h>

#define NWIRES 11
#define NLAY   4
#define NGATES 88
#define PIX    1024
#define NB     1024

typedef unsigned long long ull;

// Per gate: (c1,d1,c2,d2) = (u00.re, u00.im, u01.re, u01.im); SU(2): u10=(-c2,d2), u11=(c1,-d1)
__device__ float4 g_G[NGATES];

__global__ void precompute_gates(const float* __restrict__ w0,
                                 const float* __restrict__ w1) {
    int idx = blockIdx.x * blockDim.x + threadIdx.x;
    if (idx >= NGATES) return;
    const float PI_F = 3.14159265358979323846f;
    int k = idx / 44, rem = idx % 44;
    const float* w = (k == 0) ? w0 : w1;
    float phi   = PI_F * tanhf(w[rem * 3 + 0]);
    float theta = PI_F * tanhf(w[rem * 3 + 1]);
    float omega = PI_F * tanhf(w[rem * 3 + 2]);
    float c = cosf(0.5f * theta), s = sinf(0.5f * theta);
    float apo = 0.5f * (phi + omega), bpo = 0.5f * (phi - omega);
    float are = cosf(apo), aim = -sinf(apo);   // a = exp(-i*apo)
    float bre = cosf(bpo), bim = sinf(bpo);    // b = exp(+i*bpo)
    g_G[idx] = make_float4(are * c, aim * c, -bre * s, -bim * s);
}

// inverse CNOT-chain permutation (gather form); GF(2)-linear in dst.
__device__ __forceinline__ int cinv_idx(int dst, int r) {
    int src = dst;
    for (int q = NWIRES - 1; q >= 0; q--) {
        int cb = NWIRES - 1 - q;
        int tq = q + r; if (tq >= NWIRES) tq -= NWIRES;
        int tbit = NWIRES - 1 - tq;
        src ^= ((src >> cb) & 1) << tbit;
    }
    return src;
}
// FORWARD CNOT-chain permutation (scatter form); GF(2)-linear, C(Cinv(x))=x.
__device__ __forceinline__ int cfwd_idx(int src, int r) {
    for (int q = 0; q < NWIRES; q++) {
        int cb = NWIRES - 1 - q;
        int tq = q + r; if (tq >= NWIRES) tq -= NWIRES;
        int tbit = NWIRES - 1 - tq;
        src ^= ((src >> cb) & 1) << tbit;
    }
    return src;
}
// amp index s -> float offset of its re part in the pair smem layout
__device__ __forceinline__ int fmap(int s) { return ((s >> 1) << 2) | (s & 1); }

// ---- packed f32x2 helpers ----
__device__ __forceinline__ ull pk(float lo, float hi) {
    ull r; asm("mov.b64 %0,{%1,%2};" : "=l"(r) : "f"(lo), "f"(hi)); return r;
}
__device__ __forceinline__ void upk(ull v, float& lo, float& hi) {
    asm("mov.b64 {%0,%1},%2;" : "=f"(lo), "=f"(hi) : "l"(v));
}
__device__ __forceinline__ ull dup2(float v) { return pk(v, v); }
__device__ __forceinline__ ull m2(ull a, ull b) {
    ull d; asm("mul.rn.f32x2 %0,%1,%2;" : "=l"(d) : "l"(a), "l"(b)); return d;
}
__device__ __forceinline__ ull f2(ull a, ull b, ull c) {
    ull d; asm("fma.rn.f32x2 %0,%1,%2,%3;" : "=l"(d) : "l"(a), "l"(b), "l"(c)); return d;
}

// SU(2) gate on an inter-register bit (broadcast packed form). flip swaps 0/1 roles.
__device__ __forceinline__ void gate_reg(ull aRe[8], ull aIm[8], float4 g,
                                         int stride, bool flip) {
    float c1 = g.x, d1 = flip ? -g.y : g.y, c2 = flip ? -g.z : g.z, d2 = g.w;
    ull C1 = dup2(c1), D1 = dup2(d1), ND1 = dup2(-d1);
    ull C2 = dup2(c2), NC2 = dup2(-c2), D2 = dup2(d2), ND2 = dup2(-d2);
    #pragma unroll
    for (int j0 = 0; j0 < 8; j0++) {
        if (j0 & stride) continue;
        int j1 = j0 | stride;
        ull A0r = aRe[j0], A0i = aIm[j0], A1r = aRe[j1], A1i = aIm[j1];
        ull o0r = f2(ND2, A1i, f2(C2, A1r, f2(ND1, A0i, m2(C1, A0r))));
        ull o0i = f2(C2,  A1i, f2(D2, A1r, f2(C1,  A0i, m2(D1, A0r))));
        ull o1r = f2(D1,  A1i, f2(C1, A1r, f2(ND2, A0i, m2(NC2, A0r))));
        ull o1i = f2(C1,  A1i, f2(ND1,A1r, f2(NC2, A0i, m2(D2,  A0r))));
        aRe[j0] = o0r; aIm[j0] = o0i; aRe[j1] = o1r; aIm[j1] = o1i;
    }
}

// SU(2) gate on lane bit 0 (partner via shfl)
__device__ __forceinline__ void gate_shfl(ull aRe[8], ull aIm[8], float4 g, int hi) {
    float sd1 = hi ? -g.y : g.y;     // csy
    float sc2 = hi ? -g.z : g.z;     // cox
    ull CSX = dup2(g.x), CSY = dup2(sd1), NCSY = dup2(-sd1);
    ull COX = dup2(sc2), COY = dup2(g.w), NCOY = dup2(-g.w);
    #pragma unroll
    for (int j = 0; j < 8; j++) {
        ull Pr = __shfl_xor_sync(0xffffffffu, aRe[j], 1);
        ull Pi = __shfl_xor_sync(0xffffffffu, aIm[j], 1);
        ull Or = f2(NCOY, Pi, f2(COX, Pr, f2(NCSY, aIm[j], m2(CSX, aRe[j]))));
        ull Oi = f2(COX,  Pi, f2(COY, Pr, f2(CSX,  aIm[j], m2(CSY, aRe[j]))));
        aRe[j] = Or; aIm[j] = Oi;
    }
}

// SU(2) gate on the packing bit (intra-register butterfly via swapped halves)
__device__ __forceinline__ void gate_intra(ull aRe[8], ull aIm[8], float4 g) {
    float c1 = g.x, d1 = g.y, c2 = g.z, d2 = g.w;
    ull K1 = dup2(c1), K2 = pk(c2, -c2), K3 = pk(-d1, d1), K4 = dup2(-d2);
    ull K5 = pk(d1, -d1), K6 = dup2(d2);
    #pragma unroll
    for (int j = 0; j < 8; j++) {
        float rl, rh, il, ih;
        upk(aRe[j], rl, rh); upk(aIm[j], il, ih);
        ull Sr = pk(rh, rl), Si = pk(ih, il);
        ull Or = f2(K4, Si, f2(K3, aIm[j], f2(K2, Sr, m2(K1, aRe[j]))));
        ull Oi = f2(K2, Si, f2(K1, aIm[j], f2(K6, Sr, m2(K5, aRe[j]))));
        aRe[j] = Or; aIm[j] = Oi;
    }
}

__global__ __launch_bounds__(128, 7)
void qsim_kernel(const float* __restrict__ x,
                 const float* __restrict__ y,
                 float* __restrict__ out) {
    __shared__ float4 sp4[1024];   // pair P: (re0,re1,im0,im1) -- 16 KB single buffer
    __shared__ int fR[4][8];       // fmap(Cinv(j<<8, r))
    __shared__ int fW[4];          // fmap(Cinv(1, r))
    __shared__ int CU8[8];         // Cfwd(u<<2, 4) for the fused epilogue
    __shared__ float red[4];
    float* smf = (float*)sp4;

    const int b = blockIdx.x, t = threadIdx.x;
    const float* xb = x + (size_t)b * PIX;

    const int t31 = (t >> 1) & 7;
    const int B3x = ((t >> 1) << 4) | (t31 << 1) | (t & 1);
    const int b2  = ((t >> 4) << 7) | (t & 15);

    // ---- tiny perm tables + per-thread bases (GF(2)-linear decomposition) ----
    if (t < 32) fR[t >> 3][t & 7] = fmap(cinv_idx((t & 7) << 8, (t >> 3) + 1));
    if (t < 4)  fW[t] = fmap(cinv_idx(1, t + 1));
    if (t < 8)  CU8[t] = cfwd_idx(t << 2, 4);
    int baseR[4];
    #pragma unroll
    for (int r = 0; r < 4; r++) baseR[r] = fmap(cinv_idx(t << 1, r + 1));
    const int CS0 = cfwd_idx(2 * B3x, 4);   // forward image of this thread's base amp

    // ---- norm ----
    float ss = 0.0f;
    #pragma unroll
    for (int i = t; i < PIX; i += 128) { float v = xb[i]; ss += v * v; }
    #pragma unroll
    for (int o = 16; o > 0; o >>= 1) ss += __shfl_xor_sync(0xffffffffu, ss, o);
    if ((t & 31) == 0) red[t >> 5] = ss;
    __syncthreads();
    float inv = 1.0f / sqrtf(red[0] + red[1] + red[2] + red[3]);

    // ---- embedding: pair P = (emb[P], 0 | 0, 0) ----
    #pragma unroll
    for (int s8 = 0; s8 < 8; s8++) {
        int P = t + (s8 << 7);
        sp4[P] = make_float4(xb[P] * inv, 0.0f, 0.0f, 0.0f);
    }
    const float yhalf = 0.5f * y[b];
    const float yc = cosf(yhalf), ys = sinf(yhalf);
    __syncthreads();

    ull aRe[8], aIm[8];
    float* ob = out + (size_t)b * PIX;

    #pragma unroll 1
    for (int k = 0; k < 2; k++) {
        #pragma unroll 1
        for (int l = 0; l < NLAY; l++) {
            const int gbase = k * 44 + l * 11;
            const int pend = (k == 0 && l == 0) ? 0 : ((l == 0) ? 4 : l);

            // ===== pass 1: reg bits = i[10:8] (wires 0,1,2); perm folded into gather.
            //       Single buffer: ALL scattered reads complete (barrier after the
            //       register-only gates) before ANY linear write. =====
            if (pend == 0) {
                #pragma unroll
                for (int r = 0; r < 8; r++) {
                    float4 v = sp4[(r << 7) | t];
                    aRe[r] = pk(v.x, v.y); aIm[r] = pk(v.z, v.w);
                }
            } else {
                const int base = baseR[pend - 1], wv = fW[pend - 1];
                #pragma unroll
                for (int r = 0; r < 8; r++) {
                    int A0 = base ^ fR[pend - 1][r];
                    int A1 = A0 ^ wv;
                    aRe[r] = pk(smf[A0], smf[A1]);
                    aIm[r] = pk(smf[A0 + 2], smf[A1 + 2]);
                }
            }
            gate_reg(aRe, aIm, g_G[gbase + 0], 4, false);
            gate_reg(aRe, aIm, g_G[gbase + 1], 2, false);
            gate_reg(aRe, aIm, g_G[gbase + 2], 1, false);
            __syncthreads();   // reads-before-writes fence (race fix)
            #pragma unroll
            for (int r = 0; r < 8; r++) {
                float rl, rh, il, ih;
                upk(aRe[r], rl, rh); upk(aIm[r], il, ih);
                sp4[(r << 7) | t] = make_float4(rl, rh, il, ih);
            }
            __syncthreads();

            // ===== pass 2: reg bits = i[7:5] (wires 3,4,5); per-thread in-place safe =====
            #pragma unroll
            for (int r = 0; r < 8; r++) {
                float4 v = sp4[b2 | (r << 4)];
                aRe[r] = pk(v.x, v.y); aIm[r] = pk(v.z, v.w);
            }
            gate_reg(aRe, aIm, g_G[gbase + 3], 4, false);
            gate_reg(aRe, aIm, g_G[gbase + 4], 2, false);
            gate_reg(aRe, aIm, g_G[gbase + 5], 1, false);
            #pragma unroll
            for (int r = 0; r < 8; r++) {
                float rl, rh, il, ih;
                upk(aRe[r], rl, rh); upk(aIm[r], il, ih);
                sp4[b2 | (r << 4)] = make_float4(rl, rh, il, ih);
            }
            __syncthreads();

            // ===== pass 3: reg bits = i[4:2] (wires 6,7,8) XOR-relabeled (flip trick);
            //       wire 9 shfl on lane bit 0; wire 10 intra; per-thread in-place safe =====
            #pragma unroll
            for (int u = 0; u < 8; u++) {
                float4 v = sp4[B3x ^ (u << 1)];
                aRe[u] = pk(v.x, v.y); aIm[u] = pk(v.z, v.w);
            }
            gate_reg(aRe, aIm, g_G[gbase + 6], 4, (t31 >> 2) & 1);
            gate_reg(aRe, aIm, g_G[gbase + 7], 2, (t31 >> 1) & 1);
            gate_reg(aRe, aIm, g_G[gbase + 8], 1, t31 & 1);
            gate_shfl(aRe, aIm, g_G[gbase + 9], t & 1);
            {
                float4 G = g_G[gbase + 10];
                if (l == 0) {   // fuse RX(y): F = Rot * RX
                    float c1 = G.x, d1 = G.y, c2 = G.z, d2 = G.w;
                    G = make_float4(c1 * yc + d2 * ys, d1 * yc - c2 * ys,
                                    d1 * ys + c2 * yc, -c1 * ys + d2 * yc);
                }
                gate_intra(aRe, aIm, G);
            }

            if (k == 1 && l == NLAY - 1) {
                // ===== FUSED EPILOGUE: final CNOT perm (r=4) applied forward from
                // registers; write probs of even post-perm indices straight to gmem.
                // slot u holds pair p = B3x^(u<<1): amps s = 2*B3x ^ (u<<2) ^ h.
                // C(s) = CS0 ^ CU8[u] ^ h*C1, C1 = Cfwd(1,4) = 129 (odd).
                // Even image needs h = (CS0^CU8[u]) & 1.
                #pragma unroll
                for (int u = 0; u < 8; u++) {
                    int cs = CS0 ^ CU8[u];
                    int h = cs & 1;
                    int addr = (h ? (cs ^ 129) : cs) >> 1;
                    float rl, rh, il, ih;
                    upk(aRe[u], rl, rh); upk(aIm[u], il, ih);
                    float re = h ? rh : rl;
                    float im = h ? ih : il;
                    float pr = (re * re + im * im) * 1024.0f;
                    ob[addr] = fminf(pr, 1.0f);
                }
            } else {
                #pragma unroll
                for (int u = 0; u < 8; u++) {
                    float rl, rh, il, ih;
                    upk(aRe[u], rl, rh); upk(aIm[u], il, ih);
                    sp4[B3x ^ (u << 1)] = make_float4(rl, rh, il, ih);
                }
                __syncthreads();
            }
        }
    }
}

extern "C" void kernel_launch(void* const* d_in, const int* in_sizes, int n_in,
                              void* d_out, int out_size) {
    const float* x  = (const float*)d_in[0];
    const float* y  = (const float*)d_in[1];
    const float* w0 = (const float*)d_in[2];
    const float* w1 = (const float*)d_in[3];
    float* out = (float*)d_out;

    precompute_gates<<<1, 128>>>(w0, w1);
    qsim_kernel<<<NB, 128>>>(x, y, out);
}

// round 11
// speedup vs baseline: 1.0134x; 1.0091x over previous
#include <cuda_runtime.h>

#define NWIRES 11
#define NLAY   4
#define NGATES 88
#define PIX    1024
#define NB     1024

typedef unsigned long long ull;

// Per gate: (c1,d1,c2,d2) = (u00.re, u00.im, u01.re, u01.im); SU(2): u10=(-c2,d2), u11=(c1,-d1)
__device__ float4 g_G[NGATES];

__global__ void precompute_gates(const float* __restrict__ w0,
                                 const float* __restrict__ w1) {
    int idx = blockIdx.x * blockDim.x + threadIdx.x;
    if (idx >= NGATES) return;
    const float PI_F = 3.14159265358979323846f;
    int k = idx / 44, rem = idx % 44;
    const float* w = (k == 0) ? w0 : w1;
    float phi   = PI_F * tanhf(w[rem * 3 + 0]);
    float theta = PI_F * tanhf(w[rem * 3 + 1]);
    float omega = PI_F * tanhf(w[rem * 3 + 2]);
    float c = cosf(0.5f * theta), s = sinf(0.5f * theta);
    float apo = 0.5f * (phi + omega), bpo = 0.5f * (phi - omega);
    float are = cosf(apo), aim = -sinf(apo);   // a = exp(-i*apo)
    float bre = cosf(bpo), bim = sinf(bpo);    // b = exp(+i*bpo)
    g_G[idx] = make_float4(are * c, aim * c, -bre * s, -bim * s);
}

// inverse CNOT-chain permutation (gather form); GF(2)-linear in dst. constexpr-foldable.
__host__ __device__ constexpr int cinv_idx(int dst, int r) {
    int src = dst;
    for (int q = NWIRES - 1; q >= 0; q--) {
        int cb = NWIRES - 1 - q;
        int tq = q + r; if (tq >= NWIRES) tq -= NWIRES;
        int tbit = NWIRES - 1 - tq;
        src ^= ((src >> cb) & 1) << tbit;
    }
    return src;
}
// amp index s -> float offset of its re part in the pair smem layout
__host__ __device__ constexpr int fmap(int s) { return ((s >> 1) << 2) | (s & 1); }

// ---- packed f32x2 helpers ----
__device__ __forceinline__ ull pk(float lo, float hi) {
    ull r; asm("mov.b64 %0,{%1,%2};" : "=l"(r) : "f"(lo), "f"(hi)); return r;
}
__device__ __forceinline__ void upk(ull v, float& lo, float& hi) {
    asm("mov.b64 {%0,%1},%2;" : "=f"(lo), "=f"(hi) : "l"(v));
}
__device__ __forceinline__ ull dup2(float v) { return pk(v, v); }
__device__ __forceinline__ ull m2(ull a, ull b) {
    ull d; asm("mul.rn.f32x2 %0,%1,%2;" : "=l"(d) : "l"(a), "l"(b)); return d;
}
__device__ __forceinline__ ull f2(ull a, ull b, ull c) {
    ull d; asm("fma.rn.f32x2 %0,%1,%2,%3;" : "=l"(d) : "l"(a), "l"(b), "l"(c)); return d;
}

// SU(2) gate on an inter-register bit (broadcast packed form). flip swaps 0/1 roles.
__device__ __forceinline__ void gate_reg(ull aRe[8], ull aIm[8], float4 g,
                                         int stride, bool flip) {
    float c1 = g.x, d1 = flip ? -g.y : g.y, c2 = flip ? -g.z : g.z, d2 = g.w;
    ull C1 = dup2(c1), D1 = dup2(d1), ND1 = dup2(-d1);
    ull C2 = dup2(c2), NC2 = dup2(-c2), D2 = dup2(d2), ND2 = dup2(-d2);
    #pragma unroll
    for (int j0 = 0; j0 < 8; j0++) {
        if (j0 & stride) continue;
        int j1 = j0 | stride;
        ull A0r = aRe[j0], A0i = aIm[j0], A1r = aRe[j1], A1i = aIm[j1];
        ull o0r = f2(ND2, A1i, f2(C2, A1r, f2(ND1, A0i, m2(C1, A0r))));
        ull o0i = f2(C2,  A1i, f2(D2, A1r, f2(C1,  A0i, m2(D1, A0r))));
        ull o1r = f2(D1,  A1i, f2(C1, A1r, f2(ND2, A0i, m2(NC2, A0r))));
        ull o1i = f2(C1,  A1i, f2(ND1,A1r, f2(NC2, A0i, m2(D2,  A0r))));
        aRe[j0] = o0r; aIm[j0] = o0i; aRe[j1] = o1r; aIm[j1] = o1i;
    }
}

// SU(2) gate on lane bit 0 (partner via shfl)
__device__ __forceinline__ void gate_shfl(ull aRe[8], ull aIm[8], float4 g, int hi) {
    float sd1 = hi ? -g.y : g.y;     // csy
    float sc2 = hi ? -g.z : g.z;     // cox
    ull CSX = dup2(g.x), CSY = dup2(sd1), NCSY = dup2(-sd1);
    ull COX = dup2(sc2), COY = dup2(g.w), NCOY = dup2(-g.w);
    #pragma unroll
    for (int j = 0; j < 8; j++) {
        ull Pr = __shfl_xor_sync(0xffffffffu, aRe[j], 1);
        ull Pi = __shfl_xor_sync(0xffffffffu, aIm[j], 1);
        ull Or = f2(NCOY, Pi, f2(COX, Pr, f2(NCSY, aIm[j], m2(CSX, aRe[j]))));
        ull Oi = f2(COX,  Pi, f2(COY, Pr, f2(CSX,  aIm[j], m2(CSY, aRe[j]))));
        aRe[j] = Or; aIm[j] = Oi;
    }
}

// SU(2) gate on the packing bit (intra-register butterfly via swapped halves)
__device__ __forceinline__ void gate_intra(ull aRe[8], ull aIm[8], float4 g) {
    float c1 = g.x, d1 = g.y, c2 = g.z, d2 = g.w;
    ull K1 = dup2(c1), K2 = pk(c2, -c2), K3 = pk(-d1, d1), K4 = dup2(-d2);
    ull K5 = pk(d1, -d1), K6 = dup2(d2);
    #pragma unroll
    for (int j = 0; j < 8; j++) {
        float rl, rh, il, ih;
        upk(aRe[j], rl, rh); upk(aIm[j], il, ih);
        ull Sr = pk(rh, rl), Si = pk(ih, il);
        ull Or = f2(K4, Si, f2(K3, aIm[j], f2(K2, Sr, m2(K1, aRe[j]))));
        ull Oi = f2(K2, Si, f2(K1, aIm[j], f2(K6, Sr, m2(K5, aRe[j]))));
        aRe[j] = Or; aIm[j] = Oi;
    }
}

// Vectorized permuted gather for pend = R in {1,2,3}:
// Cfwd(e0) = e0 ^ e_{11-R}  => needed amp set closed under pair-partnering, so the
// gather is 8x LDS.128 + parity selects instead of 32x LDS.32.
// s0(j) = Cinv((j<<8)^(t<<1)); hi lane of slot j = state[s0(j)^W] = state[s0(j^M)^e0].
template<int R>
__device__ __forceinline__ void gather_vec(const float4* __restrict__ sp4,
                                           int baseR_r, ull aRe[8], ull aIm[8]) {
    constexpr int M = 1 << (3 - R);          // slot bit corresponding to e_{11-R}
    const int q0 = baseR_r >> 2;             // Cinv(t<<1) >> 1   (pair index base)
    const int p0 = baseR_r & 1;              // parity of Cinv(t<<1)
    #pragma unroll
    for (int g = 0; g < 4; g++) {
        constexpr int MM = M;                // force constexpr context
        int j0 = (g % MM) + (g / MM) * 2 * MM;   // enumerate slots with bit M clear
        int j1 = j0 | MM;
        // compile-time perm constants for the two slots
        const int d0 = cinv_idx(((g % MM) + (g / MM) * 2 * MM) << 8, R);
        const int d1 = cinv_idx((((g % MM) + (g / MM) * 2 * MM) | MM) << 8, R);
        float4 v0 = sp4[q0 ^ (d0 >> 1)];
        float4 v1 = sp4[q0 ^ (d1 >> 1)];
        const int pj0 = p0 ^ (d0 & 1);
        const int pj1 = p0 ^ (d1 & 1);
        // slot j0: lo = amp s0(j0) (parity select in v0), hi = s0(j1)^e0 (inv parity in v1)
        aRe[j0] = pk(pj0 ? v0.y : v0.x, pj1 ? v1.x : v1.y);
        aIm[j0] = pk(pj0 ? v0.w : v0.z, pj1 ? v1.z : v1.w);
        // slot j1: lo = amp s0(j1) in v1, hi = s0(j0)^e0 in v0
        aRe[j1] = pk(pj1 ? v1.y : v1.x, pj0 ? v0.x : v0.y);
        aIm[j1] = pk(pj1 ? v1.w : v1.z, pj0 ? v0.z : v0.w);
    }
}

__global__ __launch_bounds__(128, 7)
void qsim_kernel(const float* __restrict__ x,
                 const float* __restrict__ y,
                 float* __restrict__ out) {
    __shared__ float4 sp4[1024];   // pair P: (re0,re1,im0,im1) -- 16 KB single buffer
    __shared__ int fR4[8];         // fmap(Cinv(j<<8, 4))  (scalar path r=4 + epilogue)
    __shared__ float red[4];
    float* smf = (float*)sp4;

    const int b = blockIdx.x, t = threadIdx.x;
    const float* xb = x + (size_t)b * PIX;

    // ---- per-thread perm bases: baseR[r-1] = fmap(Cinv(t<<1, r)) ----
    if (t < 8) fR4[t] = fmap(cinv_idx(t << 8, 4));
    int baseR[4];
    #pragma unroll
    for (int r = 0; r < 4; r++) baseR[r] = fmap(cinv_idx(t << 1, r + 1));
    const int fW4 = fmap(cinv_idx(1, 4));

    // ---- norm ----
    float ss = 0.0f;
    #pragma unroll
    for (int i = t; i < PIX; i += 128) { float v = xb[i]; ss += v * v; }
    #pragma unroll
    for (int o = 16; o > 0; o >>= 1) ss += __shfl_xor_sync(0xffffffffu, ss, o);
    if ((t & 31) == 0) red[t >> 5] = ss;
    __syncthreads();
    float inv = 1.0f / sqrtf(red[0] + red[1] + red[2] + red[3]);

    // ---- embedding: pair P = (emb[P], 0 | 0, 0) ----
    #pragma unroll
    for (int s8 = 0; s8 < 8; s8++) {
        int P = t + (s8 << 7);
        sp4[P] = make_float4(xb[P] * inv, 0.0f, 0.0f, 0.0f);
    }
    const float yhalf = 0.5f * y[b];
    const float yc = cosf(yhalf), ys = sinf(yhalf);
    __syncthreads();

    ull aRe[8], aIm[8];
    const int t31 = (t >> 1) & 7;
    const int B3x = ((t >> 1) << 4) | (t31 << 1) | (t & 1);
    const int b2  = ((t >> 4) << 7) | (t & 15);

    #pragma unroll 1
    for (int k = 0; k < 2; k++) {
        #pragma unroll 1
        for (int l = 0; l < NLAY; l++) {
            const int gbase = k * 44 + l * 11;
            const int pend = (k == 0 && l == 0) ? 0 : ((l == 0) ? 4 : l);

            // ===== pass 1: reg bits = i[10:8] (wires 0,1,2); perm folded into gather.
            //       Single buffer: ALL scattered reads complete (barrier after the
            //       register-only gates) before ANY linear write. =====
            switch (pend) {
            case 0:
                #pragma unroll
                for (int r = 0; r < 8; r++) {
                    float4 v = sp4[(r << 7) | t];
                    aRe[r] = pk(v.x, v.y); aIm[r] = pk(v.z, v.w);
                }
                break;
            case 1: gather_vec<1>(sp4, baseR[0], aRe, aIm); break;
            case 2: gather_vec<2>(sp4, baseR[1], aRe, aIm); break;
            case 3: gather_vec<3>(sp4, baseR[2], aRe, aIm); break;
            default: {   // pend == 4: scalar path (e0-closure does not hold)
                const int base = baseR[3];
                #pragma unroll
                for (int r = 0; r < 8; r++) {
                    int A0 = base ^ fR4[r];
                    int A1 = A0 ^ fW4;
                    aRe[r] = pk(smf[A0], smf[A1]);
                    aIm[r] = pk(smf[A0 + 2], smf[A1 + 2]);
                }
            } break;
            }
            gate_reg(aRe, aIm, g_G[gbase + 0], 4, false);
            gate_reg(aRe, aIm, g_G[gbase + 1], 2, false);
            gate_reg(aRe, aIm, g_G[gbase + 2], 1, false);
            __syncthreads();   // reads-before-writes fence (race fix)
            #pragma unroll
            for (int r = 0; r < 8; r++) {
                float rl, rh, il, ih;
                upk(aRe[r], rl, rh); upk(aIm[r], il, ih);
                sp4[(r << 7) | t] = make_float4(rl, rh, il, ih);
            }
            __syncthreads();

            // ===== pass 2: reg bits = i[7:5] (wires 3,4,5); per-thread in-place safe =====
            #pragma unroll
            for (int r = 0; r < 8; r++) {
                float4 v = sp4[b2 | (r << 4)];
                aRe[r] = pk(v.x, v.y); aIm[r] = pk(v.z, v.w);
            }
            gate_reg(aRe, aIm, g_G[gbase + 3], 4, false);
            gate_reg(aRe, aIm, g_G[gbase + 4], 2, false);
            gate_reg(aRe, aIm, g_G[gbase + 5], 1, false);
            #pragma unroll
            for (int r = 0; r < 8; r++) {
                float rl, rh, il, ih;
                upk(aRe[r], rl, rh); upk(aIm[r], il, ih);
                sp4[b2 | (r << 4)] = make_float4(rl, rh, il, ih);
            }
            __syncthreads();

            // ===== pass 3: reg bits = i[4:2] (wires 6,7,8) XOR-relabeled (flip trick);
            //       wire 9 shfl on lane bit 0; wire 10 intra; per-thread in-place safe =====
            #pragma unroll
            for (int u = 0; u < 8; u++) {
                float4 v = sp4[B3x ^ (u << 1)];
                aRe[u] = pk(v.x, v.y); aIm[u] = pk(v.z, v.w);
            }
            gate_reg(aRe, aIm, g_G[gbase + 6], 4, (t31 >> 2) & 1);
            gate_reg(aRe, aIm, g_G[gbase + 7], 2, (t31 >> 1) & 1);
            gate_reg(aRe, aIm, g_G[gbase + 8], 1, t31 & 1);
            gate_shfl(aRe, aIm, g_G[gbase + 9], t & 1);
            {
                float4 G = g_G[gbase + 10];
                if (l == 0) {   // fuse RX(y): F = Rot * RX
                    float c1 = G.x, d1 = G.y, c2 = G.z, d2 = G.w;
                    G = make_float4(c1 * yc + d2 * ys, d1 * yc - c2 * ys,
                                    d1 * ys + c2 * yc, -c1 * ys + d2 * yc);
                }
                gate_intra(aRe, aIm, G);
            }
            #pragma unroll
            for (int u = 0; u < 8; u++) {
                float rl, rh, il, ih;
                upk(aRe[u], rl, rh); upk(aIm[u], il, ih);
                sp4[B3x ^ (u << 1)] = make_float4(rl, rh, il, ih);
            }
            __syncthreads();
        }
    }

    // ---- epilogue: final perm (r=4) folded; probs of even basis states ----
    float* ob = out + (size_t)b * PIX;
    const int baseo = baseR[3];
    #pragma unroll
    for (int s8 = 0; s8 < 8; s8++) {
        int addr = baseo ^ fR4[s8];
        float re = smf[addr], im = smf[addr + 2];
        float pr = (re * re + im * im) * 1024.0f;
        ob[(s8 << 7) + t] = fminf(pr, 1.0f);
    }
}

extern "C" void kernel_launch(void* const* d_in, const int* in_sizes, int n_in,
                              void* d_out, int out_size) {
    const float* x  = (const float*)d_in[0];
    const float* y  = (const float*)d_in[1];
    const float* w0 = (const float*)d_in[2];
    const float* w1 = (const float*)d_in[3];
    float* out = (float*)d_out;

    precompute_gates<<<1, 128>>>(w0, w1);
    qsim_kernel<<<NB, 128>>>(x, y, out);
}

// round 13
// speedup vs baseline: 1.0669x; 1.0528x over previous
#include <cuda_runtime.h>

#define NWIRES 11
#define NLAY   4
#define NGATES 88
#define PIX    1024
#define NB     1024

typedef unsigned long long ull;

// Per gate: (c1,d1,c2,d2) = (u00.re, u00.im, u01.re, u01.im); SU(2): u10=(-c2,d2), u11=(c1,-d1)
__device__ float4 g_G[NGATES];

__global__ void precompute_gates(const float* __restrict__ w0,
                                 const float* __restrict__ w1) {
    int idx = blockIdx.x * blockDim.x + threadIdx.x;
    if (idx >= NGATES) return;
    const float PI_F = 3.14159265358979323846f;
    int k = idx / 44, rem = idx % 44;
    const float* w = (k == 0) ? w0 : w1;
    float phi   = PI_F * tanhf(w[rem * 3 + 0]);
    float theta = PI_F * tanhf(w[rem * 3 + 1]);
    float omega = PI_F * tanhf(w[rem * 3 + 2]);
    float c = cosf(0.5f * theta), s = sinf(0.5f * theta);
    float apo = 0.5f * (phi + omega), bpo = 0.5f * (phi - omega);
    float are = cosf(apo), aim = -sinf(apo);   // a = exp(-i*apo)
    float bre = cosf(bpo), bim = sinf(bpo);    // b = exp(+i*bpo)
    g_G[idx] = make_float4(are * c, aim * c, -bre * s, -bim * s);
}

// inverse CNOT-chain permutation (gather form); GF(2)-linear in dst. constexpr-foldable.
__host__ __device__ constexpr int cinv_idx(int dst, int r) {
    int src = dst;
    for (int q = NWIRES - 1; q >= 0; q--) {
        int cb = NWIRES - 1 - q;
        int tq = q + r; if (tq >= NWIRES) tq -= NWIRES;
        int tbit = NWIRES - 1 - tq;
        src ^= ((src >> cb) & 1) << tbit;
    }
    return src;
}
// amp index s -> float offset of its re part in the pair smem layout
__host__ __device__ constexpr int fmap(int s) { return ((s >> 1) << 2) | (s & 1); }

// ---- packed f32x2 helpers ----
__device__ __forceinline__ ull pk(float lo, float hi) {
    ull r; asm("mov.b64 %0,{%1,%2};" : "=l"(r) : "f"(lo), "f"(hi)); return r;
}
__device__ __forceinline__ void upk(ull v, float& lo, float& hi) {
    asm("mov.b64 {%0,%1},%2;" : "=f"(lo), "=f"(hi) : "l"(v));
}
__device__ __forceinline__ ull dup2(float v) { return pk(v, v); }
__device__ __forceinline__ ull m2(ull a, ull b) {
    ull d; asm("mul.rn.f32x2 %0,%1,%2;" : "=l"(d) : "l"(a), "l"(b)); return d;
}
__device__ __forceinline__ ull f2(ull a, ull b, ull c) {
    ull d; asm("fma.rn.f32x2 %0,%1,%2,%3;" : "=l"(d) : "l"(a), "l"(b), "l"(c)); return d;
}

// SU(2) gate on an inter-register bit (broadcast packed form). flip swaps 0/1 roles.
__device__ __forceinline__ void gate_reg(ull aRe[8], ull aIm[8], float4 g,
                                         int stride, bool flip) {
    float c1 = g.x, d1 = flip ? -g.y : g.y, c2 = flip ? -g.z : g.z, d2 = g.w;
    ull C1 = dup2(c1), D1 = dup2(d1), ND1 = dup2(-d1);
    ull C2 = dup2(c2), NC2 = dup2(-c2), D2 = dup2(d2), ND2 = dup2(-d2);
    #pragma unroll
    for (int j0 = 0; j0 < 8; j0++) {
        if (j0 & stride) continue;
        int j1 = j0 | stride;
        ull A0r = aRe[j0], A0i = aIm[j0], A1r = aRe[j1], A1i = aIm[j1];
        ull o0r = f2(ND2, A1i, f2(C2, A1r, f2(ND1, A0i, m2(C1, A0r))));
        ull o0i = f2(C2,  A1i, f2(D2, A1r, f2(C1,  A0i, m2(D1, A0r))));
        ull o1r = f2(D1,  A1i, f2(C1, A1r, f2(ND2, A0i, m2(NC2, A0r))));
        ull o1i = f2(C1,  A1i, f2(ND1,A1r, f2(NC2, A0i, m2(D2,  A0r))));
        aRe[j0] = o0r; aIm[j0] = o0i; aRe[j1] = o1r; aIm[j1] = o1i;
    }
}

// SU(2) gate on lane bit 0 (partner via shfl)
__device__ __forceinline__ void gate_shfl(ull aRe[8], ull aIm[8], float4 g, int hi) {
    float sd1 = hi ? -g.y : g.y;     // csy
    float sc2 = hi ? -g.z : g.z;     // cox
    ull CSX = dup2(g.x), CSY = dup2(sd1), NCSY = dup2(-sd1);
    ull COX = dup2(sc2), COY = dup2(g.w), NCOY = dup2(-g.w);
    #pragma unroll
    for (int j = 0; j < 8; j++) {
        ull Pr = __shfl_xor_sync(0xffffffffu, aRe[j], 1);
        ull Pi = __shfl_xor_sync(0xffffffffu, aIm[j], 1);
        ull Or = f2(NCOY, Pi, f2(COX, Pr, f2(NCSY, aIm[j], m2(CSX, aRe[j]))));
        ull Oi = f2(COX,  Pi, f2(COY, Pr, f2(CSX,  aIm[j], m2(CSY, aRe[j]))));
        aRe[j] = Or; aIm[j] = Oi;
    }
}

// SU(2) gate on the packing bit (intra-register butterfly via swapped halves)
__device__ __forceinline__ void gate_intra(ull aRe[8], ull aIm[8], float4 g) {
    float c1 = g.x, d1 = g.y, c2 = g.z, d2 = g.w;
    ull K1 = dup2(c1), K2 = pk(c2, -c2), K3 = pk(-d1, d1), K4 = dup2(-d2);
    ull K5 = pk(d1, -d1), K6 = dup2(d2);
    #pragma unroll
    for (int j = 0; j < 8; j++) {
        float rl, rh, il, ih;
        upk(aRe[j], rl, rh); upk(aIm[j], il, ih);
        ull Sr = pk(rh, rl), Si = pk(ih, il);
        ull Or = f2(K4, Si, f2(K3, aIm[j], f2(K2, Sr, m2(K1, aRe[j]))));
        ull Oi = f2(K2, Si, f2(K1, aIm[j], f2(K6, Sr, m2(K5, aRe[j]))));
        aRe[j] = Or; aIm[j] = Oi;
    }
}

// Vectorized permuted gather for pend = R in {1,2,3}:
// Cfwd(e0) = e0 ^ e_{11-R}  => needed amp set closed under pair-partnering, so the
// gather is 8x LDS.128 + parity selects instead of 32x LDS.32.
// s0(j) = Cinv((j<<8)^(t<<1)); hi lane of slot j = state[s0(j)^W] = state[s0(j^M)^e0].
template<int R>
__device__ __forceinline__ void gather_vec(const float4* __restrict__ sp4,
                                           int baseR_r, ull aRe[8], ull aIm[8]) {
    constexpr int M = 1 << (3 - R);          // slot bit corresponding to e_{11-R}
    const int q0 = baseR_r >> 2;             // Cinv(t<<1) >> 1   (pair index base)
    const int p0 = baseR_r & 1;              // parity of Cinv(t<<1)
    #pragma unroll
    for (int g = 0; g < 4; g++) {
        constexpr int MM = M;                // force constexpr context
        int j0 = (g % MM) + (g / MM) * 2 * MM;   // enumerate slots with bit M clear
        int j1 = j0 | MM;
        // compile-time perm constants for the two slots
        const int d0 = cinv_idx(((g % MM) + (g / MM) * 2 * MM) << 8, R);
        const int d1 = cinv_idx((((g % MM) + (g / MM) * 2 * MM) | MM) << 8, R);
        float4 v0 = sp4[q0 ^ (d0 >> 1)];
        float4 v1 = sp4[q0 ^ (d1 >> 1)];
        const int pj0 = p0 ^ (d0 & 1);
        const int pj1 = p0 ^ (d1 & 1);
        // slot j0: lo = amp s0(j0) (parity select in v0), hi = s0(j1)^e0 (inv parity in v1)
        aRe[j0] = pk(pj0 ? v0.y : v0.x, pj1 ? v1.x : v1.y);
        aIm[j0] = pk(pj0 ? v0.w : v0.z, pj1 ? v1.z : v1.w);
        // slot j1: lo = amp s0(j1) in v1, hi = s0(j0)^e0 in v0
        aRe[j1] = pk(pj1 ? v1.y : v1.x, pj0 ? v0.x : v0.y);
        aIm[j1] = pk(pj1 ? v1.w : v1.z, pj0 ? v0.z : v0.w);
    }
}

__global__ __launch_bounds__(128, 7)
void qsim_kernel(const float* __restrict__ x,
                 const float* __restrict__ y,
                 float* __restrict__ out) {
    __shared__ float4 sp4[1024];   // pair P: (re0,re1,im0,im1) -- 16 KB single buffer
    __shared__ int fR4[8];         // fmap(Cinv(j<<8, 4))  (scalar path r=4 + epilogue)
    __shared__ float red[4];
    float* smf = (float*)sp4;

    const int b = blockIdx.x, t = threadIdx.x;
    const float* xb = x + (size_t)b * PIX;

    // ---- per-thread perm bases: baseR[r-1] = fmap(Cinv(t<<1, r)) ----
    if (t < 8) fR4[t] = fmap(cinv_idx(t << 8, 4));
    int baseR[4];
    #pragma unroll
    for (int r = 0; r < 4; r++) baseR[r] = fmap(cinv_idx(t << 1, r + 1));
    const int fW4 = fmap(cinv_idx(1, 4));

    // ---- norm ----
    float ss = 0.0f;
    #pragma unroll
    for (int i = t; i < PIX; i += 128) { float v = xb[i]; ss += v * v; }
    #pragma unroll
    for (int o = 16; o > 0; o >>= 1) ss += __shfl_xor_sync(0xffffffffu, ss, o);
    if ((t & 31) == 0) red[t >> 5] = ss;
    __syncthreads();
    float inv = 1.0f / sqrtf(red[0] + red[1] + red[2] + red[3]);

    // ---- embedding: pair P = (emb[P], 0 | 0, 0) ----
    #pragma unroll
    for (int s8 = 0; s8 < 8; s8++) {
        int P = t + (s8 << 7);
        sp4[P] = make_float4(xb[P] * inv, 0.0f, 0.0f, 0.0f);
    }
    const float yhalf = 0.5f * y[b];
    const float yc = cosf(yhalf), ys = sinf(yhalf);
    __syncthreads();

    ull aRe[8], aIm[8];
    const int t31 = (t >> 1) & 7;
    const int B3x = ((t >> 1) << 4) | (t31 << 1) | (t & 1);
    const int b2  = ((t >> 4) << 7) | (t & 15);

    #pragma unroll 1
    for (int k = 0; k < 2; k++) {
        #pragma unroll 1
        for (int l = 0; l < NLAY; l++) {
            const int gbase = k * 44 + l * 11;
            const int pend = (k == 0 && l == 0) ? 0 : ((l == 0) ? 4 : l);

            // ===== pass 1: reg bits = i[10:8] (wires 0,1,2); perm folded into gather.
            //       Single buffer: ALL scattered reads complete (barrier after the
            //       register-only gates) before ANY linear write. =====
            switch (pend) {
            case 0:
                #pragma unroll
                for (int r = 0; r < 8; r++) {
                    float4 v = sp4[(r << 7) | t];
                    aRe[r] = pk(v.x, v.y); aIm[r] = pk(v.z, v.w);
                }
                break;
            case 1: gather_vec<1>(sp4, baseR[0], aRe, aIm); break;
            case 2: gather_vec<2>(sp4, baseR[1], aRe, aIm); break;
            case 3: gather_vec<3>(sp4, baseR[2], aRe, aIm); break;
            default: {   // pend == 4: scalar path (e0-closure does not hold)
                const int base = baseR[3];
                #pragma unroll
                for (int r = 0; r < 8; r++) {
                    int A0 = base ^ fR4[r];
                    int A1 = A0 ^ fW4;
                    aRe[r] = pk(smf[A0], smf[A1]);
                    aIm[r] = pk(smf[A0 + 2], smf[A1 + 2]);
                }
            } break;
            }
            gate_reg(aRe, aIm, g_G[gbase + 0], 4, false);
            gate_reg(aRe, aIm, g_G[gbase + 1], 2, false);
            gate_reg(aRe, aIm, g_G[gbase + 2], 1, false);
            __syncthreads();   // reads-before-writes fence (race fix)
            #pragma unroll
            for (int r = 0; r < 8; r++) {
                float rl, rh, il, ih;
                upk(aRe[r], rl, rh); upk(aIm[r], il, ih);
                sp4[(r << 7) | t] = make_float4(rl, rh, il, ih);
            }
            __syncthreads();

            // ===== pass 2: reg bits = i[7:5] (wires 3,4,5); per-thread in-place safe =====
            #pragma unroll
            for (int r = 0; r < 8; r++) {
                float4 v = sp4[b2 | (r << 4)];
                aRe[r] = pk(v.x, v.y); aIm[r] = pk(v.z, v.w);
            }
            gate_reg(aRe, aIm, g_G[gbase + 3], 4, false);
            gate_reg(aRe, aIm, g_G[gbase + 4], 2, false);
            gate_reg(aRe, aIm, g_G[gbase + 5], 1, false);
            #pragma unroll
            for (int r = 0; r < 8; r++) {
                float rl, rh, il, ih;
                upk(aRe[r], rl, rh); upk(aIm[r], il, ih);
                sp4[b2 | (r << 4)] = make_float4(rl, rh, il, ih);
            }
            __syncthreads();

            // ===== pass 3: reg bits = i[4:2] (wires 6,7,8) XOR-relabeled (flip trick);
            //       wire 9 shfl on lane bit 0; wire 10 intra; per-thread in-place safe =====
            #pragma unroll
            for (int u = 0; u < 8; u++) {
                float4 v = sp4[B3x ^ (u << 1)];
                aRe[u] = pk(v.x, v.y); aIm[u] = pk(v.z, v.w);
            }
            gate_reg(aRe, aIm, g_G[gbase + 6], 4, (t31 >> 2) & 1);
            gate_reg(aRe, aIm, g_G[gbase + 7], 2, (t31 >> 1) & 1);
            gate_reg(aRe, aIm, g_G[gbase + 8], 1, t31 & 1);
            gate_shfl(aRe, aIm, g_G[gbase + 9], t & 1);
            {
                float4 G = g_G[gbase + 10];
                if (l == 0) {   // fuse RX(y): F = Rot * RX
                    float c1 = G.x, d1 = G.y, c2 = G.z, d2 = G.w;
                    G = make_float4(c1 * yc + d2 * ys, d1 * yc - c2 * ys,
                                    d1 * ys + c2 * yc, -c1 * ys + d2 * yc);
                }
                gate_intra(aRe, aIm, G);
            }
            #pragma unroll
            for (int u = 0; u < 8; u++) {
                float rl, rh, il, ih;
                upk(aRe[u], rl, rh); upk(aIm[u], il, ih);
                sp4[B3x ^ (u << 1)] = make_float4(rl, rh, il, ih);
            }
            __syncthreads();
        }
    }

    // ---- epilogue: final perm (r=4) folded; probs of even basis states ----
    float* ob = out + (size_t)b * PIX;
    const int baseo = baseR[3];
    #pragma unroll
    for (int s8 = 0; s8 < 8; s8++) {
        int addr = baseo ^ fR4[s8];
        float re = smf[addr], im = smf[addr + 2];
        float pr = (re * re + im * im) * 1024.0f;
        ob[(s8 << 7) + t] = fminf(pr, 1.0f);
    }
}

extern "C" void kernel_launch(void* const* d_in, const int* in_sizes, int n_in,
                              void* d_out, int out_size) {
    const float* x  = (const float*)d_in[0];
    const float* y  = (const float*)d_in[1];
    const float* w0 = (const float*)d_in[2];
    const float* w1 = (const float*)d_in[3];
    float* out = (float*)d_out;

    precompute_gates<<<1, 128>>>(w0, w1);
    qsim_kernel<<<NB, 128>>>(x, y, out);
}

// round 16
// speedup vs baseline: 1.0690x; 1.0020x over previous
#include <cuda_runtime.h>

#define NWIRES 11
#define NLAY   4
#define NGATES 88
#define PIX    1024
#define NB     1024

typedef unsigned long long ull;

// Per gate: (c1,d1,c2,d2) = (u00.re, u00.im, u01.re, u01.im); SU(2): u10=(-c2,d2), u11=(c1,-d1)
__device__ float4 g_G[NGATES];

__global__ void precompute_gates(const float* __restrict__ w0,
                                 const float* __restrict__ w1) {
    int idx = blockIdx.x * blockDim.x + threadIdx.x;
    if (idx >= NGATES) return;
    const float PI_F = 3.14159265358979323846f;
    int k = idx / 44, rem = idx % 44;
    const float* w = (k == 0) ? w0 : w1;
    float phi   = PI_F * tanhf(w[rem * 3 + 0]);
    float theta = PI_F * tanhf(w[rem * 3 + 1]);
    float omega = PI_F * tanhf(w[rem * 3 + 2]);
    float c = cosf(0.5f * theta), s = sinf(0.5f * theta);
    float apo = 0.5f * (phi + omega), bpo = 0.5f * (phi - omega);
    float are = cosf(apo), aim = -sinf(apo);   // a = exp(-i*apo)
    float bre = cosf(bpo), bim = sinf(bpo);    // b = exp(+i*bpo)
    g_G[idx] = make_float4(are * c, aim * c, -bre * s, -bim * s);
}

// inverse CNOT-chain permutation (gather form); GF(2)-linear in dst. constexpr-foldable.
__host__ __device__ constexpr int cinv_idx(int dst, int r) {
    int src = dst;
    for (int q = NWIRES - 1; q >= 0; q--) {
        int cb = NWIRES - 1 - q;
        int tq = q + r; if (tq >= NWIRES) tq -= NWIRES;
        int tbit = NWIRES - 1 - tq;
        src ^= ((src >> cb) & 1) << tbit;
    }
    return src;
}
// amp index s -> float offset of its re part in the pair smem layout
__host__ __device__ constexpr int fmap(int s) { return ((s >> 1) << 2) | (s & 1); }

// ---- packed f32x2 helpers ----
__device__ __forceinline__ ull pk(float lo, float hi) {
    ull r; asm("mov.b64 %0,{%1,%2};" : "=l"(r) : "f"(lo), "f"(hi)); return r;
}
__device__ __forceinline__ void upk(ull v, float& lo, float& hi) {
    asm("mov.b64 {%0,%1},%2;" : "=f"(lo), "=f"(hi) : "l"(v));
}
__device__ __forceinline__ ull dup2(float v) { return pk(v, v); }
__device__ __forceinline__ ull m2(ull a, ull b) {
    ull d; asm("mul.rn.f32x2 %0,%1,%2;" : "=l"(d) : "l"(a), "l"(b)); return d;
}
__device__ __forceinline__ ull f2(ull a, ull b, ull c) {
    ull d; asm("fma.rn.f32x2 %0,%1,%2,%3;" : "=l"(d) : "l"(a), "l"(b), "l"(c)); return d;
}

// SU(2) gate on an inter-register bit (broadcast packed form). flip swaps 0/1 roles.
__device__ __forceinline__ void gate_reg(ull aRe[8], ull aIm[8], float4 g,
                                         int stride, bool flip) {
    float c1 = g.x, d1 = flip ? -g.y : g.y, c2 = flip ? -g.z : g.z, d2 = g.w;
    ull C1 = dup2(c1), D1 = dup2(d1), ND1 = dup2(-d1);
    ull C2 = dup2(c2), NC2 = dup2(-c2), D2 = dup2(d2), ND2 = dup2(-d2);
    #pragma unroll
    for (int j0 = 0; j0 < 8; j0++) {
        if (j0 & stride) continue;
        int j1 = j0 | stride;
        ull A0r = aRe[j0], A0i = aIm[j0], A1r = aRe[j1], A1i = aIm[j1];
        ull o0r = f2(ND2, A1i, f2(C2, A1r, f2(ND1, A0i, m2(C1, A0r))));
        ull o0i = f2(C2,  A1i, f2(D2, A1r, f2(C1,  A0i, m2(D1, A0r))));
        ull o1r = f2(D1,  A1i, f2(C1, A1r, f2(ND2, A0i, m2(NC2, A0r))));
        ull o1i = f2(C1,  A1i, f2(ND1,A1r, f2(NC2, A0i, m2(D2,  A0r))));
        aRe[j0] = o0r; aIm[j0] = o0i; aRe[j1] = o1r; aIm[j1] = o1i;
    }
}

// SU(2) gate on lane bit 0 (partner via shfl)
__device__ __forceinline__ void gate_shfl(ull aRe[8], ull aIm[8], float4 g, int hi) {
    float sd1 = hi ? -g.y : g.y;     // csy
    float sc2 = hi ? -g.z : g.z;     // cox
    ull CSX = dup2(g.x), CSY = dup2(sd1), NCSY = dup2(-sd1);
    ull COX = dup2(sc2), COY = dup2(g.w), NCOY = dup2(-g.w);
    #pragma unroll
    for (int j = 0; j < 8; j++) {
        ull Pr = __shfl_xor_sync(0xffffffffu, aRe[j], 1);
        ull Pi = __shfl_xor_sync(0xffffffffu, aIm[j], 1);
        ull Or = f2(NCOY, Pi, f2(COX, Pr, f2(NCSY, aIm[j], m2(CSX, aRe[j]))));
        ull Oi = f2(COX,  Pi, f2(COY, Pr, f2(CSX,  aIm[j], m2(CSY, aRe[j]))));
        aRe[j] = Or; aIm[j] = Oi;
    }
}

// SU(2) gate on the packing bit (intra-register butterfly via swapped halves)
__device__ __forceinline__ void gate_intra(ull aRe[8], ull aIm[8], float4 g) {
    float c1 = g.x, d1 = g.y, c2 = g.z, d2 = g.w;
    ull K1 = dup2(c1), K2 = pk(c2, -c2), K3 = pk(-d1, d1), K4 = dup2(-d2);
    ull K5 = pk(d1, -d1), K6 = dup2(d2);
    #pragma unroll
    for (int j = 0; j < 8; j++) {
        float rl, rh, il, ih;
        upk(aRe[j], rl, rh); upk(aIm[j], il, ih);
        ull Sr = pk(rh, rl), Si = pk(ih, il);
        ull Or = f2(K4, Si, f2(K3, aIm[j], f2(K2, Sr, m2(K1, aRe[j]))));
        ull Oi = f2(K2, Si, f2(K1, aIm[j], f2(K6, Sr, m2(K5, aRe[j]))));
        aRe[j] = Or; aIm[j] = Oi;
    }
}

// Vectorized permuted gather for pend = R in {1,2,3}:
// Cfwd(e0) = e0 ^ e_{11-R}  => needed amp set closed under pair-partnering, so the
// gather is 8x LDS.128 + parity selects instead of 32x LDS.32.
template<int R>
__device__ __forceinline__ void gather_vec(const float4* __restrict__ sp4,
                                           int baseR_r, ull aRe[8], ull aIm[8]) {
    constexpr int M = 1 << (3 - R);          // slot bit corresponding to e_{11-R}
    const int q0 = baseR_r >> 2;             // Cinv(t<<1) >> 1   (pair index base)
    const int p0 = baseR_r & 1;              // parity of Cinv(t<<1)
    #pragma unroll
    for (int g = 0; g < 4; g++) {
        constexpr int MM = M;                // force constexpr context
        int j0 = (g % MM) + (g / MM) * 2 * MM;   // enumerate slots with bit M clear
        int j1 = j0 | MM;
        // compile-time perm constants for the two slots
        const int d0 = cinv_idx(((g % MM) + (g / MM) * 2 * MM) << 8, R);
        const int d1 = cinv_idx((((g % MM) + (g / MM) * 2 * MM) | MM) << 8, R);
        float4 v0 = sp4[q0 ^ (d0 >> 1)];
        float4 v1 = sp4[q0 ^ (d1 >> 1)];
        const int pj0 = p0 ^ (d0 & 1);
        const int pj1 = p0 ^ (d1 & 1);
        // slot j0: lo = amp s0(j0) (parity select in v0), hi = s0(j1)^e0 (inv parity in v1)
        aRe[j0] = pk(pj0 ? v0.y : v0.x, pj1 ? v1.x : v1.y);
        aIm[j0] = pk(pj0 ? v0.w : v0.z, pj1 ? v1.z : v1.w);
        // slot j1: lo = amp s0(j1) in v1, hi = s0(j0)^e0 in v0
        aRe[j1] = pk(pj1 ? v1.y : v1.x, pj0 ? v0.x : v0.y);
        aIm[j1] = pk(pj1 ? v1.w : v1.z, pj0 ? v0.z : v0.w);
    }
}

__global__ __launch_bounds__(128, 7)
void qsim_kernel(const float* __restrict__ x,
                 const float* __restrict__ y,
                 float* __restrict__ out) {
    __shared__ float4 sp4[1024];   // pair P: (re0,re1,im0,im1) -- 16 KB single buffer
    __shared__ int fR4[8];         // fmap(Cinv(j<<8, 4))  (scalar path r=4 + epilogue)
    __shared__ float red[4];
    float* smf = (float*)sp4;

    const int b = blockIdx.x, t = threadIdx.x;
    const float* xb = x + (size_t)b * PIX;

    // ---- per-thread perm bases: baseR[r-1] = fmap(Cinv(t<<1, r)) ----
    if (t < 8) fR4[t] = fmap(cinv_idx(t << 8, 4));
    int baseR[4];
    #pragma unroll
    for (int r = 0; r < 4; r++) baseR[r] = fmap(cinv_idx(t << 1, r + 1));
    const int fW4 = fmap(cinv_idx(1, 4));

    // ---- norm ----
    float ss = 0.0f;
    #pragma unroll
    for (int i = t; i < PIX; i += 128) { float v = xb[i]; ss += v * v; }
    #pragma unroll
    for (int o = 16; o > 0; o >>= 1) ss += __shfl_xor_sync(0xffffffffu, ss, o);
    if ((t & 31) == 0) red[t >> 5] = ss;
    __syncthreads();
    float inv = 1.0f / sqrtf(red[0] + red[1] + red[2] + red[3]);

    // ---- embedding: pair P = (emb[P], 0 | 0, 0) ----
    #pragma unroll
    for (int s8 = 0; s8 < 8; s8++) {
        int P = t + (s8 << 7);
        sp4[P] = make_float4(xb[P] * inv, 0.0f, 0.0f, 0.0f);
    }
    const float yhalf = 0.5f * y[b];
    const float yc = cosf(yhalf), ys = sinf(yhalf);
    __syncthreads();

    ull aRe[8], aIm[8];
    const int t31 = (t >> 1) & 7;
    const int B3x = ((t >> 1) << 4) | (t31 << 1) | (t & 1);
    const int b2  = ((t >> 4) << 7) | (t & 15);

    #pragma unroll 1
    for (int k = 0; k < 2; k++) {
        #pragma unroll 1
        for (int l = 0; l < NLAY; l++) {
            const int gbase = k * 44 + l * 11;
            const int pend = (k == 0 && l == 0) ? 0 : ((l == 0) ? 4 : l);

            // ===== pass 1: reg bits = i[10:8] (wires 0,1,2); perm folded into gather.
            //       Single buffer: scattered reads complete block-wide (fence barrier
            //       after the register-only gates) before any linear write. For pend==0
            //       the read-set == write-set per thread -> fence not needed. =====
            switch (pend) {
            case 0:
                #pragma unroll
                for (int r = 0; r < 8; r++) {
                    float4 v = sp4[(r << 7) | t];
                    aRe[r] = pk(v.x, v.y); aIm[r] = pk(v.z, v.w);
                }
                break;
            case 1: gather_vec<1>(sp4, baseR[0], aRe, aIm); break;
            case 2: gather_vec<2>(sp4, baseR[1], aRe, aIm); break;
            case 3: gather_vec<3>(sp4, baseR[2], aRe, aIm); break;
            default: {   // pend == 4: scalar path (e0-closure does not hold)
                const int base = baseR[3];
                #pragma unroll
                for (int r = 0; r < 8; r++) {
                    int A0 = base ^ fR4[r];
                    int A1 = A0 ^ fW4;
                    aRe[r] = pk(smf[A0], smf[A1]);
                    aIm[r] = pk(smf[A0 + 2], smf[A1 + 2]);
                }
            } break;
            }
            gate_reg(aRe, aIm, g_G[gbase + 0], 4, false);
            gate_reg(aRe, aIm, g_G[gbase + 1], 2, false);
            gate_reg(aRe, aIm, g_G[gbase + 2], 1, false);
            if (pend != 0) __syncthreads();   // reads-before-writes fence (uniform branch)
            #pragma unroll
            for (int r = 0; r < 8; r++) {
                float rl, rh, il, ih;
                upk(aRe[r], rl, rh); upk(aIm[r], il, ih);
                sp4[(r << 7) | t] = make_float4(rl, rh, il, ih);
            }
            __syncthreads();   // pass1 writes are read cross-warp by pass2

            // ===== pass 2: reg bits = i[7:5] (wires 3,4,5); per-thread in-place safe =====
            #pragma unroll
            for (int r = 0; r < 8; r++) {
                float4 v = sp4[b2 | (r << 4)];
                aRe[r] = pk(v.x, v.y); aIm[r] = pk(v.z, v.w);
            }
            gate_reg(aRe, aIm, g_G[gbase + 3], 4, false);
            gate_reg(aRe, aIm, g_G[gbase + 4], 2, false);
            gate_reg(aRe, aIm, g_G[gbase + 5], 1, false);
            #pragma unroll
            for (int r = 0; r < 8; r++) {
                float rl, rh, il, ih;
                upk(aRe[r], rl, rh); upk(aIm[r], il, ih);
                sp4[b2 | (r << 4)] = make_float4(rl, rh, il, ih);
            }
            // pass2 -> pass3 dependency is INTRA-WARP only:
            // pass3 reads addr A with A[9:7]=t[6:4]; pass2 writer of A has
            // t'[6:4]=A[9:7] => t'[6:5]=t[6:5] (same warp). Warp sync suffices.
            __syncwarp();

            // ===== pass 3: reg bits = i[4:2] (wires 6,7,8) XOR-relabeled (flip trick);
            //       wire 9 shfl on lane bit 0; wire 10 intra; per-thread in-place safe =====
            #pragma unroll
            for (int u = 0; u < 8; u++) {
                float4 v = sp4[B3x ^ (u << 1)];
                aRe[u] = pk(v.x, v.y); aIm[u] = pk(v.z, v.w);
            }
            gate_reg(aRe, aIm, g_G[gbase + 6], 4, (t31 >> 2) & 1);
            gate_reg(aRe, aIm, g_G[gbase + 7], 2, (t31 >> 1) & 1);
            gate_reg(aRe, aIm, g_G[gbase + 8], 1, t31 & 1);
            gate_shfl(aRe, aIm, g_G[gbase + 9], t & 1);
            {
                float4 G = g_G[gbase + 10];
                if (l == 0) {   // fuse RX(y): F = Rot * RX
                    float c1 = G.x, d1 = G.y, c2 = G.z, d2 = G.w;
                    G = make_float4(c1 * yc + d2 * ys, d1 * yc - c2 * ys,
                                    d1 * ys + c2 * yc, -c1 * ys + d2 * yc);
                }
                gate_intra(aRe, aIm, G);
            }
            #pragma unroll
            for (int u = 0; u < 8; u++) {
                float rl, rh, il, ih;
                upk(aRe[u], rl, rh); upk(aIm[u], il, ih);
                sp4[B3x ^ (u << 1)] = make_float4(rl, rh, il, ih);
            }
            __syncthreads();   // pass3 writes feed the next layer's global gather
        }
    }

    // ---- epilogue: final perm (r=4) folded; probs of even basis states ----
    float* ob = out + (size_t)b * PIX;
    const int baseo = baseR[3];
    #pragma unroll
    for (int s8 = 0; s8 < 8; s8++) {
        int addr = baseo ^ fR4[s8];
        float re = smf[addr], im = smf[addr + 2];
        float pr = (re * re + im * im) * 1024.0f;
        ob[(s8 << 7) + t] = fminf(pr, 1.0f);
    }
}

extern "C" void kernel_launch(void* const* d_in, const int* in_sizes, int n_in,
                              void* d_out, int out_size) {
    const float* x  = (const float*)d_in[0];
    const float* y  = (const float*)d_in[1];
    const float* w0 = (const float*)d_in[2];
    const float* w1 = (const float*)d_in[3];
    float* out = (float*)d_out;

    precompute_gates<<<1, 128>>>(w0, w1);
    qsim_kernel<<<NB, 128>>>(x, y, out);
}